// round 4
// baseline (speedup 1.0000x reference)
#include <cuda_runtime.h>
#include <cuda_bf16.h>

// Fused gauge-transport kernel:
//   out[b] = expm(0.5*(omega[e] - omega[e]^T)) @ J[b],  e = edge_indices[b]
// Taylor series in matvec form (order 6): y = sum_{k=0..6} X^k J / k!
// ||X||_2 ~ 0.05 -> truncation error ~1e-11, far under the 1e-3 gate.
// One thread per transport event. omega row gathered via 16x LDG.128.
//
// NOTE: edge_indices is int32 on device (JAX silently downcasts int64
// without JAX_ENABLE_X64). Reading it as int64 was the R3 fault.

#define K 8

__global__ void __launch_bounds__(256, 2)
gauge_transport_kernel(const float* __restrict__ omega,
                       const float* __restrict__ J,
                       const int* __restrict__ edge_idx,
                       float* __restrict__ out,
                       int B)
{
    int b = blockIdx.x * blockDim.x + threadIdx.x;
    if (b >= B) return;

    long long e = (long long)edge_idx[b];

    // Gather omega[e] : 64 floats = 16 x LDG.128, front-batched for MLP.
    const float4* __restrict__ op =
        reinterpret_cast<const float4*>(omega + (e << 6));
    float X[K][K];
    #pragma unroll
    for (int i = 0; i < K; i++) {
        float4 a = op[2 * i];
        float4 c = op[2 * i + 1];
        X[i][0] = a.x; X[i][1] = a.y; X[i][2] = a.z; X[i][3] = a.w;
        X[i][4] = c.x; X[i][5] = c.y; X[i][6] = c.z; X[i][7] = c.w;
    }

    // Load J[b] (two LDG.128, contiguous per thread)
    const float4* __restrict__ jp =
        reinterpret_cast<const float4*>(J + ((long long)b << 3));
    float4 j0 = jp[0], j1 = jp[1];
    float v[K] = { j0.x, j0.y, j0.z, j0.w, j1.x, j1.y, j1.z, j1.w };

    // Skew-symmetrize in place: X = 0.5*(X - X^T)
    #pragma unroll
    for (int i = 0; i < K; i++) {
        X[i][i] = 0.0f;
        #pragma unroll
        for (int j = i + 1; j < K; j++) {
            float s = 0.5f * (X[i][j] - X[j][i]);
            X[i][j] = s;
            X[j][i] = -s;
        }
    }

    // Taylor: acc = v; t = v; for k: t = (X@t)/(k+1); acc += t;
    float acc[K], t[K];
    #pragma unroll
    for (int i = 0; i < K; i++) { acc[i] = v[i]; t[i] = v[i]; }

    const float invk[6] = { 1.0f, 0.5f, 1.0f / 3.0f, 0.25f, 0.2f, 1.0f / 6.0f };
    #pragma unroll
    for (int k = 0; k < 6; k++) {
        float nt[K];
        #pragma unroll
        for (int i = 0; i < K; i++) {
            float s = X[i][0] * t[0];
            #pragma unroll
            for (int j = 1; j < K; j++) s = fmaf(X[i][j], t[j], s);
            nt[i] = s * invk[k];
        }
        #pragma unroll
        for (int i = 0; i < K; i++) { t[i] = nt[i]; acc[i] += nt[i]; }
    }

    // Store: two STG.128, contiguous per thread
    float4* __restrict__ outp =
        reinterpret_cast<float4*>(out + ((long long)b << 3));
    outp[0] = make_float4(acc[0], acc[1], acc[2], acc[3]);
    outp[1] = make_float4(acc[4], acc[5], acc[6], acc[7]);
}

extern "C" void kernel_launch(void* const* d_in, const int* in_sizes, int n_in,
                              void* d_out, int out_size)
{
    const float* omega    = (const float*)d_in[0];   // (E, 8, 8) float32
    const float* J        = (const float*)d_in[1];   // (B, 8)    float32
    const int*   edge_idx = (const int*)d_in[2];     // (B,)      int32 (JAX x64 off)
    // d_in[3] = edges (E,2) — unused by the reference computation

    float* out = (float*)d_out;
    int B = in_sizes[2];   // element count of edge_indices

    int threads = 256;
    int blocks = (B + threads - 1) / threads;
    gauge_transport_kernel<<<blocks, threads>>>(omega, J, edge_idx, out, B);
}